// round 3
// baseline (speedup 1.0000x reference)
#include <cuda_runtime.h>
#include <math.h>

// ---- problem dims ----
#define Tn 4096      // B*S tokens
#define Dn 768
#define Hn 12
#define DHn 64
#define Sn 512
#define Bsz 8
#define En 8
#define Fn 3072
#define TOPK 2

// ---- scratch (device globals: allocation-free per harness rules) ----
__device__ float g_h1[Tn * Dn];
__device__ float g_q[Tn * Dn];
__device__ float g_k[Tn * Dn];
__device__ float g_v[Tn * Dn];
__device__ float g_att[Tn * Dn];
__device__ float g_x1[Tn * Dn];
__device__ float g_h2[Tn * Dn];
__device__ float g_mid[(size_t)Tn * TOPK * Fn];   // ~100 MB
__device__ float g_eout[Tn * TOPK * Dn];          // ~25 MB
__device__ int   g_idx[Tn * TOPK];
__device__ float g_gate[Tn * TOPK];
__device__ int   g_pos[Tn * TOPK];
__device__ int   g_slotof[Tn * TOPK];
__device__ int   g_slot2tok[Tn * TOPK];
__device__ int   g_counts[En];
__device__ int   g_offsets[En];

// ---- helpers ----
__device__ __forceinline__ float gelu_tanh(float x) {
    const float c = 0.7978845608028654f;   // sqrt(2/pi)
    float t = tanhf(c * (x + 0.044715f * x * x * x));
    return 0.5f * x * (1.0f + t);
}

// ---------------------------------------------------------------------------
// LayerNorm: one block per token, 256 threads, D=768 (3 elems/thread)
// ---------------------------------------------------------------------------
__global__ void ln_kernel(const float* __restrict__ x,
                          const float* __restrict__ g,
                          const float* __restrict__ b,
                          float* __restrict__ out) {
    int t = blockIdx.x;
    const float* row = x + (size_t)t * Dn;
    int tid = threadIdx.x;
    float v0 = row[tid], v1 = row[tid + 256], v2 = row[tid + 512];
    float s  = v0 + v1 + v2;
    float ss = v0 * v0 + v1 * v1 + v2 * v2;
    #pragma unroll
    for (int o = 16; o; o >>= 1) {
        s  += __shfl_down_sync(0xffffffffu, s, o);
        ss += __shfl_down_sync(0xffffffffu, ss, o);
    }
    __shared__ float rs[8], rss[8];
    __shared__ float mu_s, rstd_s;
    int w = tid >> 5, l = tid & 31;
    if (l == 0) { rs[w] = s; rss[w] = ss; }
    __syncthreads();
    if (tid == 0) {
        float S = 0.f, SS = 0.f;
        #pragma unroll
        for (int i = 0; i < 8; i++) { S += rs[i]; SS += rss[i]; }
        float mu  = S / (float)Dn;
        float var = SS / (float)Dn - mu * mu;
        mu_s = mu; rstd_s = rsqrtf(var + 1e-5f);
    }
    __syncthreads();
    float mu = mu_s, rstd = rstd_s;
    float* orow = out + (size_t)t * Dn;
    orow[tid]       = (v0 - mu) * rstd * g[tid]       + b[tid];
    orow[tid + 256] = (v1 - mu) * rstd * g[tid + 256] + b[tid + 256];
    orow[tid + 512] = (v2 - mu) * rstd * g[tid + 512] + b[tid + 512];
}

// ---------------------------------------------------------------------------
// Tiled SGEMM 64x64x16, 256 threads, 4x4 microtile. M,N,K all multiples.
// ---------------------------------------------------------------------------
__global__ void __launch_bounds__(256)
sgemm_plain(const float* __restrict__ A, const float* __restrict__ B,
            float* __restrict__ C, int N, int Kd) {
    __shared__ float As[16][64];
    __shared__ float Bs[16][64];
    int bm = blockIdx.x * 64, bn = blockIdx.y * 64;
    int t = threadIdx.x;
    int tr = t >> 4, tc = t & 15;
    int am = t >> 2, ak = (t & 3) << 2;
    int bk = t >> 4, bn4 = (t & 15) << 2;
    float acc[4][4] = {};
    const float* Ap = A + (size_t)(bm + am) * Kd + ak;
    const float* Bp = B + (size_t)bk * N + bn + bn4;
    for (int k0 = 0; k0 < Kd; k0 += 16) {
        float4 a = *(const float4*)(Ap + k0);
        As[ak][am] = a.x; As[ak + 1][am] = a.y; As[ak + 2][am] = a.z; As[ak + 3][am] = a.w;
        *(float4*)(&Bs[bk][bn4]) = *(const float4*)(Bp + (size_t)k0 * N);
        __syncthreads();
        #pragma unroll
        for (int kk = 0; kk < 16; kk++) {
            float ra[4], rb[4];
            #pragma unroll
            for (int i = 0; i < 4; i++) ra[i] = As[kk][(tr << 2) + i];
            #pragma unroll
            for (int j = 0; j < 4; j++) rb[j] = Bs[kk][(tc << 2) + j];
            #pragma unroll
            for (int i = 0; i < 4; i++)
                #pragma unroll
                for (int j = 0; j < 4; j++) acc[i][j] += ra[i] * rb[j];
        }
        __syncthreads();
    }
    #pragma unroll
    for (int i = 0; i < 4; i++)
        #pragma unroll
        for (int j = 0; j < 4; j++)
            C[(size_t)(bm + (tr << 2) + i) * N + bn + (tc << 2) + j] = acc[i][j];
}

// Same, with residual add: C = R + A@B
__global__ void __launch_bounds__(256)
sgemm_resid(const float* __restrict__ A, const float* __restrict__ B,
            const float* __restrict__ R, float* __restrict__ C, int N, int Kd) {
    __shared__ float As[16][64];
    __shared__ float Bs[16][64];
    int bm = blockIdx.x * 64, bn = blockIdx.y * 64;
    int t = threadIdx.x;
    int tr = t >> 4, tc = t & 15;
    int am = t >> 2, ak = (t & 3) << 2;
    int bk = t >> 4, bn4 = (t & 15) << 2;
    float acc[4][4] = {};
    const float* Ap = A + (size_t)(bm + am) * Kd + ak;
    const float* Bp = B + (size_t)bk * N + bn + bn4;
    for (int k0 = 0; k0 < Kd; k0 += 16) {
        float4 a = *(const float4*)(Ap + k0);
        As[ak][am] = a.x; As[ak + 1][am] = a.y; As[ak + 2][am] = a.z; As[ak + 3][am] = a.w;
        *(float4*)(&Bs[bk][bn4]) = *(const float4*)(Bp + (size_t)k0 * N);
        __syncthreads();
        #pragma unroll
        for (int kk = 0; kk < 16; kk++) {
            float ra[4], rb[4];
            #pragma unroll
            for (int i = 0; i < 4; i++) ra[i] = As[kk][(tr << 2) + i];
            #pragma unroll
            for (int j = 0; j < 4; j++) rb[j] = Bs[kk][(tc << 2) + j];
            #pragma unroll
            for (int i = 0; i < 4; i++)
                #pragma unroll
                for (int j = 0; j < 4; j++) acc[i][j] += ra[i] * rb[j];
        }
        __syncthreads();
    }
    #pragma unroll
    for (int i = 0; i < 4; i++) {
        int r = bm + (tr << 2) + i;
        #pragma unroll
        for (int j = 0; j < 4; j++) {
            int n = bn + (tc << 2) + j;
            C[(size_t)r * N + n] = R[(size_t)r * N + n] + acc[i][j];
        }
    }
}

// ---------------------------------------------------------------------------
// Flash-style attention: grid (S/128, H, B), 128 threads; one thread = one q row.
// ---------------------------------------------------------------------------
__global__ void __launch_bounds__(128)
attn_kernel(const float* __restrict__ q, const float* __restrict__ k,
            const float* __restrict__ v, float* __restrict__ o_out) {
    const int KT = 32;
    int h = blockIdx.y, b = blockIdx.z;
    int tid = threadIdx.x;
    int qrow = b * Sn + blockIdx.x * 128 + tid;
    const float* qptr = q + (size_t)qrow * Dn + h * DHn;
    float qreg[64];
    #pragma unroll
    for (int d = 0; d < 64; d++) qreg[d] = qptr[d] * 0.125f;  // 1/sqrt(64)
    float oacc[64];
    #pragma unroll
    for (int d = 0; d < 64; d++) oacc[d] = 0.f;
    float m = -1e30f, lsum = 0.f;

    __shared__ float Ks[KT][64], Vs[KT][64];
    for (int k0 = 0; k0 < Sn; k0 += KT) {
        for (int i = tid; i < KT * 64; i += 128) {
            int r = i >> 6, c = i & 63;
            size_t src = (size_t)(b * Sn + k0 + r) * Dn + h * DHn + c;
            Ks[r][c] = k[src];
            Vs[r][c] = v[src];
        }
        __syncthreads();
        float sv[KT];
        float smax = -1e30f;
        #pragma unroll
        for (int j = 0; j < KT; j++) {
            float s = 0.f;
            #pragma unroll
            for (int d = 0; d < 64; d++) s += qreg[d] * Ks[j][d];
            sv[j] = s;
            smax = fmaxf(smax, s);
        }
        float mnew = fmaxf(m, smax);
        float alpha = expf(m - mnew);
        float psum = 0.f;
        #pragma unroll
        for (int j = 0; j < KT; j++) { float p = expf(sv[j] - mnew); sv[j] = p; psum += p; }
        lsum = lsum * alpha + psum;
        #pragma unroll
        for (int d = 0; d < 64; d++) {
            float a = 0.f;
            #pragma unroll
            for (int j = 0; j < KT; j++) a += sv[j] * Vs[j][d];
            oacc[d] = oacc[d] * alpha + a;
        }
        m = mnew;
        __syncthreads();
    }
    float inv = 1.0f / lsum;
    float* op = o_out + (size_t)qrow * Dn + h * DHn;
    #pragma unroll
    for (int d = 0; d < 64; d++) op[d] = oacc[d] * inv;
}

// ---------------------------------------------------------------------------
// MoE routing: one block per token; warp e computes logit e; thread 0 does top-2.
// ---------------------------------------------------------------------------
__global__ void zero_counts_kernel() {
    if (threadIdx.x < En) g_counts[threadIdx.x] = 0;
}

__global__ void routing_kernel(const float* __restrict__ h2,
                               const float* __restrict__ gate_w,
                               const float* __restrict__ gate_b,
                               const float* __restrict__ bias_e) {
    int t = blockIdx.x;
    int wid = threadIdx.x >> 5, lane = threadIdx.x & 31;
    __shared__ float logit[En];
    float s = 0.f;
    const float* row = h2 + (size_t)t * Dn;
    for (int d = lane; d < Dn; d += 32) s += row[d] * gate_w[d * En + wid];
    #pragma unroll
    for (int o = 16; o; o >>= 1) s += __shfl_down_sync(0xffffffffu, s, o);
    if (lane == 0) logit[wid] = s + gate_b[wid];   // TAU = 1
    __syncthreads();
    if (threadIdx.x == 0) {
        float sel[En];
        #pragma unroll
        for (int e = 0; e < En; e++) sel[e] = logit[e] + bias_e[e];
        int i0 = 0;
        #pragma unroll
        for (int e = 1; e < En; e++) if (sel[e] > sel[i0]) i0 = e;
        int i1 = (i0 == 0) ? 1 : 0;
        #pragma unroll
        for (int e = 0; e < En; e++) if (e != i0 && sel[e] > sel[i1]) i1 = e;
        float l0 = logit[i0], l1 = logit[i1];
        float mm = fmaxf(l0, l1);
        float e0 = expf(l0 - mm), e1 = expf(l1 - mm);
        float inv = 1.0f / (e0 + e1);
        g_idx[t * 2] = i0;     g_idx[t * 2 + 1] = i1;
        g_gate[t * 2] = e0 * inv; g_gate[t * 2 + 1] = e1 * inv;
        g_pos[t * 2]     = atomicAdd(&g_counts[i0], 1);
        g_pos[t * 2 + 1] = atomicAdd(&g_counts[i1], 1);
    }
}

__global__ void offsets_kernel() {
    if (threadIdx.x == 0) {
        int acc = 0;
        for (int e = 0; e < En; e++) { g_offsets[e] = acc; acc += g_counts[e]; }
    }
}

__global__ void fill_slots_kernel() {
    int t = blockIdx.x * 256 + threadIdx.x;
    if (t >= Tn) return;
    #pragma unroll
    for (int kk = 0; kk < 2; kk++) {
        int e = g_idx[t * 2 + kk];
        int slot = g_offsets[e] + g_pos[t * 2 + kk];
        g_slotof[t * 2 + kk] = slot;
        g_slot2tok[slot] = t;
    }
}

// ---------------------------------------------------------------------------
// MoE FFN1: gathered GEMM per expert, gelu(X@w1[e] + b1[e]) -> g_mid
// grid (T/64, F/64, E)
// ---------------------------------------------------------------------------
__global__ void __launch_bounds__(256)
moe_ffn1(const float* __restrict__ h2, const float* __restrict__ w1,
         const float* __restrict__ b1) {
    int e = blockIdx.z;
    int cnt = g_counts[e];
    int bm = blockIdx.x * 64;
    if (bm >= cnt) return;
    int off = g_offsets[e];
    int bn = blockIdx.y * 64;

    __shared__ float As[16][64];
    __shared__ float Bs[16][64];
    int t = threadIdx.x;
    int tr = t >> 4, tc = t & 15;
    int am = t >> 2, ak = (t & 3) << 2;
    int bk = t >> 4, bn4 = (t & 15) << 2;
    float acc[4][4] = {};

    int arow = bm + am;
    int tok = g_slot2tok[off + (arow < cnt ? arow : 0)];
    const float* Ap = h2 + (size_t)tok * Dn + ak;
    const float* Bp = w1 + (size_t)e * Dn * Fn + (size_t)bk * Fn + bn + bn4;

    for (int k0 = 0; k0 < Dn; k0 += 16) {
        float4 a = *(const float4*)(Ap + k0);
        As[ak][am] = a.x; As[ak + 1][am] = a.y; As[ak + 2][am] = a.z; As[ak + 3][am] = a.w;
        *(float4*)(&Bs[bk][bn4]) = *(const float4*)(Bp + (size_t)k0 * Fn);
        __syncthreads();
        #pragma unroll
        for (int kk = 0; kk < 16; kk++) {
            float ra[4], rb[4];
            #pragma unroll
            for (int i = 0; i < 4; i++) ra[i] = As[kk][(tr << 2) + i];
            #pragma unroll
            for (int j = 0; j < 4; j++) rb[j] = Bs[kk][(tc << 2) + j];
            #pragma unroll
            for (int i = 0; i < 4; i++)
                #pragma unroll
                for (int j = 0; j < 4; j++) acc[i][j] += ra[i] * rb[j];
        }
        __syncthreads();
    }
    #pragma unroll
    for (int i = 0; i < 4; i++) {
        int r = bm + (tr << 2) + i;
        if (r < cnt) {
            #pragma unroll
            for (int j = 0; j < 4; j++) {
                int n = bn + (tc << 2) + j;
                float val = acc[i][j] + b1[e * Fn + n];
                g_mid[(size_t)(off + r) * Fn + n] = gelu_tanh(val);
            }
        }
    }
}

// ---------------------------------------------------------------------------
// MoE FFN2: per-expert GEMM, mid@w2[e] + b2[e] -> g_eout
// grid (T/64, D/64, E)
// ---------------------------------------------------------------------------
__global__ void __launch_bounds__(256)
moe_ffn2(const float* __restrict__ w2, const float* __restrict__ b2) {
    int e = blockIdx.z;
    int cnt = g_counts[e];
    int bm = blockIdx.x * 64;
    if (bm >= cnt) return;
    int off = g_offsets[e];
    int bn = blockIdx.y * 64;

    __shared__ float As[16][64];
    __shared__ float Bs[16][64];
    int t = threadIdx.x;
    int tr = t >> 4, tc = t & 15;
    int am = t >> 2, ak = (t & 3) << 2;
    int bk = t >> 4, bn4 = (t & 15) << 2;
    float acc[4][4] = {};

    int arow = bm + am;
    int aslot = off + (arow < cnt ? arow : 0);
    const float* Ap = g_mid + (size_t)aslot * Fn + ak;
    const float* Bp = w2 + (size_t)e * Fn * Dn + (size_t)bk * Dn + bn + bn4;

    for (int k0 = 0; k0 < Fn; k0 += 16) {
        float4 a = *(const float4*)(Ap + k0);
        As[ak][am] = a.x; As[ak + 1][am] = a.y; As[ak + 2][am] = a.z; As[ak + 3][am] = a.w;
        *(float4*)(&Bs[bk][bn4]) = *(const float4*)(Bp + (size_t)k0 * Dn);
        __syncthreads();
        #pragma unroll
        for (int kk = 0; kk < 16; kk++) {
            float ra[4], rb[4];
            #pragma unroll
            for (int i = 0; i < 4; i++) ra[i] = As[kk][(tr << 2) + i];
            #pragma unroll
            for (int j = 0; j < 4; j++) rb[j] = Bs[kk][(tc << 2) + j];
            #pragma unroll
            for (int i = 0; i < 4; i++)
                #pragma unroll
                for (int j = 0; j < 4; j++) acc[i][j] += ra[i] * rb[j];
        }
        __syncthreads();
    }
    #pragma unroll
    for (int i = 0; i < 4; i++) {
        int r = bm + (tr << 2) + i;
        if (r < cnt) {
            #pragma unroll
            for (int j = 0; j < 4; j++) {
                int n = bn + (tc << 2) + j;
                g_eout[(size_t)(off + r) * Dn + n] = acc[i][j] + b2[e * Dn + n];
            }
        }
    }
}

// ---------------------------------------------------------------------------
// Final combine: out = x1 + g0*eout[slot0] + g1*eout[slot1]
// grid (T, D/256)
// ---------------------------------------------------------------------------
__global__ void combine_kernel(const float* __restrict__ x1, float* __restrict__ out) {
    int t = blockIdx.x;
    int d = blockIdx.y * 256 + threadIdx.x;
    int s0 = g_slotof[t * 2], s1 = g_slotof[t * 2 + 1];
    float g0 = g_gate[t * 2], g1 = g_gate[t * 2 + 1];
    out[(size_t)t * Dn + d] = x1[(size_t)t * Dn + d]
                            + g0 * g_eout[(size_t)s0 * Dn + d]
                            + g1 * g_eout[(size_t)s1 * Dn + d];
}

// ---------------------------------------------------------------------------
// launch
// ---------------------------------------------------------------------------
extern "C" void kernel_launch(void* const* d_in, const int* in_sizes, int n_in,
                              void* d_out, int out_size) {
    const float* x      = (const float*)d_in[0];
    const float* wq     = (const float*)d_in[1];
    const float* wk     = (const float*)d_in[2];
    const float* wv     = (const float*)d_in[3];
    const float* wo     = (const float*)d_in[4];
    const float* ln1_g  = (const float*)d_in[5];
    const float* ln1_b  = (const float*)d_in[6];
    const float* ln2_g  = (const float*)d_in[7];
    const float* ln2_b  = (const float*)d_in[8];
    const float* gate_w = (const float*)d_in[9];
    const float* gate_b = (const float*)d_in[10];
    const float* bias_e = (const float*)d_in[11];
    const float* w1     = (const float*)d_in[12];
    const float* b1     = (const float*)d_in[13];
    const float* w2     = (const float*)d_in[14];
    const float* b2     = (const float*)d_in[15];
    float* out = (float*)d_out;

    float *h1, *qb, *kb, *vb, *att, *x1, *h2;
    cudaGetSymbolAddress((void**)&h1,  g_h1);
    cudaGetSymbolAddress((void**)&qb,  g_q);
    cudaGetSymbolAddress((void**)&kb,  g_k);
    cudaGetSymbolAddress((void**)&vb,  g_v);
    cudaGetSymbolAddress((void**)&att, g_att);
    cudaGetSymbolAddress((void**)&x1,  g_x1);
    cudaGetSymbolAddress((void**)&h2,  g_h2);

    // --- attention block ---
    ln_kernel<<<Tn, 256>>>(x, ln1_g, ln1_b, h1);
    dim3 gproj(Tn / 64, Dn / 64);
    sgemm_plain<<<gproj, 256>>>(h1, wq, qb, Dn, Dn);
    sgemm_plain<<<gproj, 256>>>(h1, wk, kb, Dn, Dn);
    sgemm_plain<<<gproj, 256>>>(h1, wv, vb, Dn, Dn);
    attn_kernel<<<dim3(Sn / 128, Hn, Bsz), 128>>>(qb, kb, vb, att);
    sgemm_resid<<<gproj, 256>>>(att, wo, x, x1, Dn, Dn);

    // --- MoE block ---
    ln_kernel<<<Tn, 256>>>(x1, ln2_g, ln2_b, h2);
    zero_counts_kernel<<<1, 32>>>();
    routing_kernel<<<Tn, 256>>>(h2, gate_w, gate_b, bias_e);
    offsets_kernel<<<1, 32>>>();
    fill_slots_kernel<<<Tn / 256, 256>>>();
    moe_ffn1<<<dim3(Tn / 64, Fn / 64, En), 256>>>(h2, w1, b1);
    moe_ffn2<<<dim3(Tn / 64, Dn / 64, En), 256>>>(w2, b2);
    combine_kernel<<<dim3(Tn, Dn / 256), 256>>>(x1, out);
}

// round 4
// speedup vs baseline: 1.0568x; 1.0568x over previous
#include <cuda_runtime.h>
#include <math.h>

// ---- problem dims ----
#define Tn 4096      // B*S tokens
#define Dn 768
#define Hn 12
#define DHn 64
#define Sn 512
#define Bsz 8
#define En 8
#define Fn 3072
#define TOPK 2

#define BM 128
#define BN 128
#define BK 16

// ---- scratch (device globals: allocation-free per harness rules) ----
__device__ float g_h1[Tn * Dn];
__device__ float g_q[Tn * Dn];
__device__ float g_k[Tn * Dn];
__device__ float g_v[Tn * Dn];
__device__ float g_att[Tn * Dn];
__device__ float g_x1[Tn * Dn];
__device__ float g_h2[Tn * Dn];
__device__ float g_mid[(size_t)Tn * TOPK * Fn];   // ~100 MB
__device__ float g_eout[Tn * TOPK * Dn];          // ~25 MB
__device__ int   g_idx[Tn * TOPK];
__device__ float g_gate[Tn * TOPK];
__device__ int   g_pos[Tn * TOPK];
__device__ int   g_slotof[Tn * TOPK];
__device__ int   g_slot2tok[Tn * TOPK];
__device__ int   g_counts[En];
__device__ int   g_offsets[En];

// ---- helpers ----
__device__ __forceinline__ float gelu_tanh(float x) {
    const float c = 0.7978845608028654f;   // sqrt(2/pi)
    float t = tanhf(c * (x + 0.044715f * x * x * x));
    return 0.5f * x * (1.0f + t);
}

// ---------------------------------------------------------------------------
// GEMM core: 128x128 tile, BK=16, 256 threads, 8x8 microtile,
// double-buffered smem with register-staged global prefetch.
// Thread mapping:
//   A load: row = t>>1 (0..127), kc = (t&1)*8  -> 2 float4 along K, store transposed
//   B load: krow = t>>4 (0..15), nc = (t&15)*8 -> 2 float4 along N
//   compute: tr8 = (t>>4)*8 rows, tc8 = (t&15)*8 cols
// ---------------------------------------------------------------------------
__device__ __forceinline__ void gemm_core(
    const float* __restrict__ aptr,   // A global: this thread's row base + kc
    const float* __restrict__ bptr,   // B global: krow-th row + (bn + nc)
    int ldb, int iters,
    float (&acc)[8][8],
    float (*As)[BM], float (*Bs)[BN],
    int row, int kc, int krow, int nc, int tr8, int tc8)
{
    float4 a0 = *(const float4*)(aptr);
    float4 a1 = *(const float4*)(aptr + 4);
    float4 b0 = *(const float4*)(bptr);
    float4 b1 = *(const float4*)(bptr + 4);

    As[kc + 0][row] = a0.x; As[kc + 1][row] = a0.y;
    As[kc + 2][row] = a0.z; As[kc + 3][row] = a0.w;
    As[kc + 4][row] = a1.x; As[kc + 5][row] = a1.y;
    As[kc + 6][row] = a1.z; As[kc + 7][row] = a1.w;
    *(float4*)&Bs[krow][nc]     = b0;
    *(float4*)&Bs[krow][nc + 4] = b1;
    __syncthreads();

    int buf = 0;
    for (int it = 0; it < iters; it++) {
        if (it + 1 < iters) {
            const float* ap = aptr + (it + 1) * BK;
            a0 = *(const float4*)(ap);
            a1 = *(const float4*)(ap + 4);
            const float* bp = bptr + (size_t)(it + 1) * BK * ldb;
            b0 = *(const float4*)(bp);
            b1 = *(const float4*)(bp + 4);
        }
        float (*Ac)[BM] = As + buf * BK;
        float (*Bc)[BN] = Bs + buf * BK;
        #pragma unroll
        for (int kk = 0; kk < BK; kk++) {
            float ar[8], br[8];
            *(float4*)(ar)     = *(const float4*)&Ac[kk][tr8];
            *(float4*)(ar + 4) = *(const float4*)&Ac[kk][tr8 + 4];
            *(float4*)(br)     = *(const float4*)&Bc[kk][tc8];
            *(float4*)(br + 4) = *(const float4*)&Bc[kk][tc8 + 4];
            #pragma unroll
            for (int i = 0; i < 8; i++)
                #pragma unroll
                for (int j = 0; j < 8; j++)
                    acc[i][j] += ar[i] * br[j];
        }
        if (it + 1 < iters) {
            float (*An)[BM] = As + (buf ^ 1) * BK;
            float (*Bn)[BN] = Bs + (buf ^ 1) * BK;
            An[kc + 0][row] = a0.x; An[kc + 1][row] = a0.y;
            An[kc + 2][row] = a0.z; An[kc + 3][row] = a0.w;
            An[kc + 4][row] = a1.x; An[kc + 5][row] = a1.y;
            An[kc + 6][row] = a1.z; An[kc + 7][row] = a1.w;
            *(float4*)&Bn[krow][nc]     = b0;
            *(float4*)&Bn[krow][nc + 4] = b1;
        }
        __syncthreads();
        buf ^= 1;
    }
}

#define GEMM_THREAD_IDX()               \
    int t    = threadIdx.x;             \
    int row  = t >> 1;                  \
    int kc   = (t & 1) * 8;             \
    int krow = t >> 4;                  \
    int nc   = (t & 15) * 8;            \
    int tr8  = (t >> 4) * 8;            \
    int tc8  = (t & 15) * 8;            \
    __shared__ float As[2 * BK][BM];    \
    __shared__ float Bs[2 * BK][BN];    \
    float acc[8][8] = {};

// ---------------------------------------------------------------------------
// Fused QKV projection: grid (Tn/128, Dn/128, 3)
// ---------------------------------------------------------------------------
__global__ void __launch_bounds__(256, 2)
qkv_gemm(const float* __restrict__ h1,
         const float* __restrict__ wq, const float* __restrict__ wk,
         const float* __restrict__ wv) {
    const float* W = (blockIdx.z == 0) ? wq : (blockIdx.z == 1) ? wk : wv;
    float* C = (blockIdx.z == 0) ? g_q : (blockIdx.z == 1) ? g_k : g_v;
    int bm = blockIdx.x * BM, bn = blockIdx.y * BN;
    GEMM_THREAD_IDX();
    gemm_core(h1 + (size_t)(bm + row) * Dn + kc,
              W + (size_t)krow * Dn + bn + nc,
              Dn, Dn / BK, acc, As, Bs, row, kc, krow, nc, tr8, tc8);
    #pragma unroll
    for (int i = 0; i < 8; i++) {
        float* cp = C + (size_t)(bm + tr8 + i) * Dn + bn + tc8;
        *(float4*)(cp)     = *(float4*)&acc[i][0];
        *(float4*)(cp + 4) = *(float4*)&acc[i][4];
    }
}

// ---------------------------------------------------------------------------
// O projection + residual: x1 = x + att @ wo.  grid (Tn/128, Dn/128)
// ---------------------------------------------------------------------------
__global__ void __launch_bounds__(256, 2)
oproj_gemm(const float* __restrict__ wo, const float* __restrict__ x) {
    int bm = blockIdx.x * BM, bn = blockIdx.y * BN;
    GEMM_THREAD_IDX();
    gemm_core(g_att + (size_t)(bm + row) * Dn + kc,
              wo + (size_t)krow * Dn + bn + nc,
              Dn, Dn / BK, acc, As, Bs, row, kc, krow, nc, tr8, tc8);
    #pragma unroll
    for (int i = 0; i < 8; i++) {
        size_t base = (size_t)(bm + tr8 + i) * Dn + bn + tc8;
        float4 r0 = *(const float4*)(x + base);
        float4 r1 = *(const float4*)(x + base + 4);
        float4 o0, o1;
        o0.x = r0.x + acc[i][0]; o0.y = r0.y + acc[i][1];
        o0.z = r0.z + acc[i][2]; o0.w = r0.w + acc[i][3];
        o1.x = r1.x + acc[i][4]; o1.y = r1.y + acc[i][5];
        o1.z = r1.z + acc[i][6]; o1.w = r1.w + acc[i][7];
        *(float4*)(g_x1 + base)     = o0;
        *(float4*)(g_x1 + base + 4) = o1;
    }
}

// ---------------------------------------------------------------------------
// MoE FFN1: gathered rows, gelu(X@w1[e] + b1[e]) -> g_mid
// grid (Tn/128, Fn/128, E)
// ---------------------------------------------------------------------------
__global__ void __launch_bounds__(256, 2)
moe_ffn1(const float* __restrict__ h2, const float* __restrict__ w1,
         const float* __restrict__ b1) {
    int e = blockIdx.z;
    int cnt = g_counts[e];
    int bm = blockIdx.x * BM;
    if (bm >= cnt) return;
    int off = g_offsets[e];
    int bn = blockIdx.y * BN;
    GEMM_THREAD_IDX();
    int arow = bm + row; if (arow >= cnt) arow = cnt - 1;
    int tok = g_slot2tok[off + arow];
    gemm_core(h2 + (size_t)tok * Dn + kc,
              w1 + (size_t)e * Dn * Fn + (size_t)krow * Fn + bn + nc,
              Fn, Dn / BK, acc, As, Bs, row, kc, krow, nc, tr8, tc8);
    float bv[8];
    #pragma unroll
    for (int j = 0; j < 8; j++) bv[j] = b1[e * Fn + bn + tc8 + j];
    #pragma unroll
    for (int i = 0; i < 8; i++) {
        int r = bm + tr8 + i;
        if (r < cnt) {
            float* cp = g_mid + (size_t)(off + r) * Fn + bn + tc8;
            float4 o0, o1;
            o0.x = gelu_tanh(acc[i][0] + bv[0]); o0.y = gelu_tanh(acc[i][1] + bv[1]);
            o0.z = gelu_tanh(acc[i][2] + bv[2]); o0.w = gelu_tanh(acc[i][3] + bv[3]);
            o1.x = gelu_tanh(acc[i][4] + bv[4]); o1.y = gelu_tanh(acc[i][5] + bv[5]);
            o1.z = gelu_tanh(acc[i][6] + bv[6]); o1.w = gelu_tanh(acc[i][7] + bv[7]);
            *(float4*)(cp)     = o0;
            *(float4*)(cp + 4) = o1;
        }
    }
}

// ---------------------------------------------------------------------------
// MoE FFN2: mid@w2[e] + b2[e] -> g_eout.  grid (Tn/128, Dn/128, E)
// ---------------------------------------------------------------------------
__global__ void __launch_bounds__(256, 2)
moe_ffn2(const float* __restrict__ w2, const float* __restrict__ b2) {
    int e = blockIdx.z;
    int cnt = g_counts[e];
    int bm = blockIdx.x * BM;
    if (bm >= cnt) return;
    int off = g_offsets[e];
    int bn = blockIdx.y * BN;
    GEMM_THREAD_IDX();
    int arow = bm + row; if (arow >= cnt) arow = cnt - 1;
    gemm_core(g_mid + (size_t)(off + arow) * Fn + kc,
              w2 + (size_t)e * Fn * Dn + (size_t)krow * Dn + bn + nc,
              Dn, Fn / BK, acc, As, Bs, row, kc, krow, nc, tr8, tc8);
    float bv[8];
    #pragma unroll
    for (int j = 0; j < 8; j++) bv[j] = b2[e * Dn + bn + tc8 + j];
    #pragma unroll
    for (int i = 0; i < 8; i++) {
        int r = bm + tr8 + i;
        if (r < cnt) {
            float* cp = g_eout + (size_t)(off + r) * Dn + bn + tc8;
            float4 o0, o1;
            o0.x = acc[i][0] + bv[0]; o0.y = acc[i][1] + bv[1];
            o0.z = acc[i][2] + bv[2]; o0.w = acc[i][3] + bv[3];
            o1.x = acc[i][4] + bv[4]; o1.y = acc[i][5] + bv[5];
            o1.z = acc[i][6] + bv[6]; o1.w = acc[i][7] + bv[7];
            *(float4*)(cp)     = o0;
            *(float4*)(cp + 4) = o1;
        }
    }
}

// ---------------------------------------------------------------------------
// LayerNorm: one block per token, 256 threads, D=768 (3 elems/thread)
// ---------------------------------------------------------------------------
__global__ void ln_kernel(const float* __restrict__ x,
                          const float* __restrict__ g,
                          const float* __restrict__ b,
                          float* __restrict__ out) {
    int t = blockIdx.x;
    const float* row = x + (size_t)t * Dn;
    int tid = threadIdx.x;
    float v0 = row[tid], v1 = row[tid + 256], v2 = row[tid + 512];
    float s  = v0 + v1 + v2;
    float ss = v0 * v0 + v1 * v1 + v2 * v2;
    #pragma unroll
    for (int o = 16; o; o >>= 1) {
        s  += __shfl_down_sync(0xffffffffu, s, o);
        ss += __shfl_down_sync(0xffffffffu, ss, o);
    }
    __shared__ float rs[8], rss[8];
    __shared__ float mu_s, rstd_s;
    int w = tid >> 5, l = tid & 31;
    if (l == 0) { rs[w] = s; rss[w] = ss; }
    __syncthreads();
    if (tid == 0) {
        float S = 0.f, SS = 0.f;
        #pragma unroll
        for (int i = 0; i < 8; i++) { S += rs[i]; SS += rss[i]; }
        float mu  = S / (float)Dn;
        float var = SS / (float)Dn - mu * mu;
        mu_s = mu; rstd_s = rsqrtf(var + 1e-5f);
    }
    __syncthreads();
    float mu = mu_s, rstd = rstd_s;
    float* orow = out + (size_t)t * Dn;
    orow[tid]       = (v0 - mu) * rstd * g[tid]       + b[tid];
    orow[tid + 256] = (v1 - mu) * rstd * g[tid + 256] + b[tid + 256];
    orow[tid + 512] = (v2 - mu) * rstd * g[tid + 512] + b[tid + 512];
}

// ---------------------------------------------------------------------------
// Flash-style attention: grid (S/128, H, B), 128 threads; one thread = one q row.
// ---------------------------------------------------------------------------
__global__ void __launch_bounds__(128)
attn_kernel(const float* __restrict__ q, const float* __restrict__ k,
            const float* __restrict__ v, float* __restrict__ o_out) {
    const int KT = 32;
    int h = blockIdx.y, b = blockIdx.z;
    int tid = threadIdx.x;
    int qrow = b * Sn + blockIdx.x * 128 + tid;
    const float* qptr = q + (size_t)qrow * Dn + h * DHn;
    float qreg[64];
    #pragma unroll
    for (int d = 0; d < 64; d++) qreg[d] = qptr[d] * 0.125f;  // 1/sqrt(64)
    float oacc[64];
    #pragma unroll
    for (int d = 0; d < 64; d++) oacc[d] = 0.f;
    float m = -1e30f, lsum = 0.f;

    __shared__ float Ks[KT][64], Vs[KT][64];
    for (int k0 = 0; k0 < Sn; k0 += KT) {
        for (int i = tid; i < KT * 64; i += 128) {
            int r = i >> 6, c = i & 63;
            size_t src = (size_t)(b * Sn + k0 + r) * Dn + h * DHn + c;
            Ks[r][c] = k[src];
            Vs[r][c] = v[src];
        }
        __syncthreads();
        float sv[KT];
        float smax = -1e30f;
        #pragma unroll
        for (int j = 0; j < KT; j++) {
            float s = 0.f;
            #pragma unroll
            for (int d = 0; d < 64; d++) s += qreg[d] * Ks[j][d];
            sv[j] = s;
            smax = fmaxf(smax, s);
        }
        float mnew = fmaxf(m, smax);
        float alpha = expf(m - mnew);
        float psum = 0.f;
        #pragma unroll
        for (int j = 0; j < KT; j++) { float p = expf(sv[j] - mnew); sv[j] = p; psum += p; }
        lsum = lsum * alpha + psum;
        #pragma unroll
        for (int d = 0; d < 64; d++) {
            float a = 0.f;
            #pragma unroll
            for (int j = 0; j < KT; j++) a += sv[j] * Vs[j][d];
            oacc[d] = oacc[d] * alpha + a;
        }
        m = mnew;
        __syncthreads();
    }
    float inv = 1.0f / lsum;
    float* op = o_out + (size_t)qrow * Dn + h * DHn;
    #pragma unroll
    for (int d = 0; d < 64; d++) op[d] = oacc[d] * inv;
}

// ---------------------------------------------------------------------------
// MoE routing
// ---------------------------------------------------------------------------
__global__ void zero_counts_kernel() {
    if (threadIdx.x < En) g_counts[threadIdx.x] = 0;
}

__global__ void routing_kernel(const float* __restrict__ h2,
                               const float* __restrict__ gate_w,
                               const float* __restrict__ gate_b,
                               const float* __restrict__ bias_e) {
    int t = blockIdx.x;
    int wid = threadIdx.x >> 5, lane = threadIdx.x & 31;
    __shared__ float logit[En];
    float s = 0.f;
    const float* row = h2 + (size_t)t * Dn;
    for (int d = lane; d < Dn; d += 32) s += row[d] * gate_w[d * En + wid];
    #pragma unroll
    for (int o = 16; o; o >>= 1) s += __shfl_down_sync(0xffffffffu, s, o);
    if (lane == 0) logit[wid] = s + gate_b[wid];   // TAU = 1
    __syncthreads();
    if (threadIdx.x == 0) {
        float sel[En];
        #pragma unroll
        for (int e = 0; e < En; e++) sel[e] = logit[e] + bias_e[e];
        int i0 = 0;
        #pragma unroll
        for (int e = 1; e < En; e++) if (sel[e] > sel[i0]) i0 = e;
        int i1 = (i0 == 0) ? 1 : 0;
        #pragma unroll
        for (int e = 0; e < En; e++) if (e != i0 && sel[e] > sel[i1]) i1 = e;
        float l0 = logit[i0], l1 = logit[i1];
        float mm = fmaxf(l0, l1);
        float e0 = expf(l0 - mm), e1 = expf(l1 - mm);
        float inv = 1.0f / (e0 + e1);
        g_idx[t * 2] = i0;     g_idx[t * 2 + 1] = i1;
        g_gate[t * 2] = e0 * inv; g_gate[t * 2 + 1] = e1 * inv;
        g_pos[t * 2]     = atomicAdd(&g_counts[i0], 1);
        g_pos[t * 2 + 1] = atomicAdd(&g_counts[i1], 1);
    }
}

__global__ void offsets_kernel() {
    if (threadIdx.x == 0) {
        int acc = 0;
        for (int e = 0; e < En; e++) { g_offsets[e] = acc; acc += g_counts[e]; }
    }
}

__global__ void fill_slots_kernel() {
    int t = blockIdx.x * 256 + threadIdx.x;
    if (t >= Tn) return;
    #pragma unroll
    for (int kk = 0; kk < 2; kk++) {
        int e = g_idx[t * 2 + kk];
        int slot = g_offsets[e] + g_pos[t * 2 + kk];
        g_slotof[t * 2 + kk] = slot;
        g_slot2tok[slot] = t;
    }
}

// ---------------------------------------------------------------------------
// Final combine: out = x1 + g0*eout[slot0] + g1*eout[slot1]
// ---------------------------------------------------------------------------
__global__ void combine_kernel(const float* __restrict__ x1, float* __restrict__ out) {
    int t = blockIdx.x;
    int d = blockIdx.y * 256 + threadIdx.x;
    int s0 = g_slotof[t * 2], s1 = g_slotof[t * 2 + 1];
    float g0 = g_gate[t * 2], g1 = g_gate[t * 2 + 1];
    out[(size_t)t * Dn + d] = x1[(size_t)t * Dn + d]
                            + g0 * g_eout[(size_t)s0 * Dn + d]
                            + g1 * g_eout[(size_t)s1 * Dn + d];
}

// ---------------------------------------------------------------------------
// launch
// ---------------------------------------------------------------------------
extern "C" void kernel_launch(void* const* d_in, const int* in_sizes, int n_in,
                              void* d_out, int out_size) {
    const float* x      = (const float*)d_in[0];
    const float* wq     = (const float*)d_in[1];
    const float* wk     = (const float*)d_in[2];
    const float* wv     = (const float*)d_in[3];
    const float* wo     = (const float*)d_in[4];
    const float* ln1_g  = (const float*)d_in[5];
    const float* ln1_b  = (const float*)d_in[6];
    const float* ln2_g  = (const float*)d_in[7];
    const float* ln2_b  = (const float*)d_in[8];
    const float* gate_w = (const float*)d_in[9];
    const float* gate_b = (const float*)d_in[10];
    const float* bias_e = (const float*)d_in[11];
    const float* w1     = (const float*)d_in[12];
    const float* b1     = (const float*)d_in[13];
    const float* w2     = (const float*)d_in[14];
    const float* b2     = (const float*)d_in[15];
    float* out = (float*)d_out;

    float *h1, *qb, *kb, *vb, *att, *x1, *h2;
    cudaGetSymbolAddress((void**)&h1,  g_h1);
    cudaGetSymbolAddress((void**)&qb,  g_q);
    cudaGetSymbolAddress((void**)&kb,  g_k);
    cudaGetSymbolAddress((void**)&vb,  g_v);
    cudaGetSymbolAddress((void**)&att, g_att);
    cudaGetSymbolAddress((void**)&x1,  g_x1);
    cudaGetSymbolAddress((void**)&h2,  g_h2);

    // --- attention block ---
    ln_kernel<<<Tn, 256>>>(x, ln1_g, ln1_b, h1);
    qkv_gemm<<<dim3(Tn / BM, Dn / BN, 3), 256>>>(h1, wq, wk, wv);
    attn_kernel<<<dim3(Sn / 128, Hn, Bsz), 128>>>(qb, kb, vb, att);
    oproj_gemm<<<dim3(Tn / BM, Dn / BN), 256>>>(wo, x);

    // --- MoE block ---
    ln_kernel<<<Tn, 256>>>(x1, ln2_g, ln2_b, h2);
    zero_counts_kernel<<<1, 32>>>();
    routing_kernel<<<Tn, 256>>>(h2, gate_w, gate_b, bias_e);
    offsets_kernel<<<1, 32>>>();
    fill_slots_kernel<<<Tn / 256, 256>>>();
    moe_ffn1<<<dim3(Tn / BM, Fn / BN, En), 256>>>(h2, w1, b1);
    moe_ffn2<<<dim3(Tn / BM, Dn / BN, En), 256>>>(w2, b2);
    combine_kernel<<<dim3(Tn, Dn / 256), 256>>>(x1, out);
}

// round 6
// speedup vs baseline: 2.3681x; 2.2409x over previous
#include <cuda_runtime.h>
#include <math.h>
#include <stdint.h>

// ---- problem dims ----
#define Tn 4096      // B*S tokens
#define Dn 768
#define Hn 12
#define DHn 64
#define Sn 512
#define Bsz 8
#define En 8
#define Fn 3072
#define TOPK 2

#define BM 128
#define BN 128
#define BK 16
#define LDSW 136   // smem row stride in words; mod 32 = 8 -> conflict-free frags

// ---- scratch (device globals: allocation-free per harness rules) ----
__device__ float g_h1[Tn * Dn];
__device__ float g_q[Tn * Dn];
__device__ float g_k[Tn * Dn];
__device__ float g_v[Tn * Dn];
__device__ float g_att[Tn * Dn];
__device__ float g_x1[Tn * Dn];
__device__ float g_h2[Tn * Dn];
__device__ float g_mid[(size_t)Tn * TOPK * Fn];   // ~100 MB
__device__ float g_eout[Tn * TOPK * Dn];          // ~25 MB
__device__ int   g_idx[Tn * TOPK];
__device__ float g_gate[Tn * TOPK];
__device__ int   g_pos[Tn * TOPK];
__device__ int   g_slotof[Tn * TOPK];
__device__ int   g_slot2tok[Tn * TOPK];
__device__ int   g_counts[En];
__device__ int   g_offsets[En];

// ---- helpers ----
__device__ __forceinline__ float gelu_tanh(float x) {
    const float c = 0.7978845608028654f;   // sqrt(2/pi)
    float t = tanhf(c * (x + 0.044715f * x * x * x));
    return 0.5f * x * (1.0f + t);
}

__device__ __forceinline__ uint32_t f2tf(float x) {
    uint32_t r;
    asm("cvt.rna.tf32.f32 %0, %1;" : "=r"(r) : "f"(x));
    return r;
}

__device__ __forceinline__ void mma_tf32(float* cc,
    uint32_t a0, uint32_t a1, uint32_t a2, uint32_t a3,
    uint32_t b0, uint32_t b1) {
    asm volatile(
        "mma.sync.aligned.m16n8k8.row.col.f32.tf32.tf32.f32 "
        "{%0,%1,%2,%3},{%4,%5,%6,%7},{%8,%9},{%0,%1,%2,%3};"
        : "+f"(cc[0]), "+f"(cc[1]), "+f"(cc[2]), "+f"(cc[3])
        : "r"(a0), "r"(a1), "r"(a2), "r"(a3), "r"(b0), "r"(b1));
}

// ---------------------------------------------------------------------------
// tf32 tensor-core GEMM core: 128x128 tile, BK=16, 256 threads (8 warps),
// warp tile 64x32 (4 Mfrags x 4 Nfrags of m16n8k8), fp32 accumulate.
// Double-buffered smem, register-staged global prefetch, 1 sync per K-tile.
// Smem layout: As[k][m] (A transposed to k-major), Bs[k][n], stride LDSW=136.
// Staging: A: row=t>>1, kc=(t&1)*8 (2x float4 along K, transposed on store)
//          B: krow=t>>4, nc=(t&15)*8 (2x float4 along N)
// Fragments (m16n8k8.tf32 per PTX ISA): g=lane>>2, c=lane&3
//   a0=(g,c) a1=(g+8,c) a2=(g,c+4) a3=(g+8,c+4)
//   b0=(c,g) b1=(c+4,g);  cN: rows {g,g+8}, cols {2c,2c+1}
// ---------------------------------------------------------------------------
__device__ __forceinline__ void gemm_core_tf32(
    const float* __restrict__ aptr,   // A global: thread row base + kc
    const float* __restrict__ bptr,   // B global: krow row + bn + nc
    int ldb, int iters,
    float (&acc)[16][4],
    uint32_t (*As)[LDSW], uint32_t (*Bs)[LDSW],
    int row, int kc, int krow, int nc,
    int g, int c, int m0base, int n0base)
{
    float4 a0 = *(const float4*)(aptr);
    float4 a1 = *(const float4*)(aptr + 4);
    float4 b0 = *(const float4*)(bptr);
    float4 b1 = *(const float4*)(bptr + 4);

    As[kc + 0][row] = f2tf(a0.x); As[kc + 1][row] = f2tf(a0.y);
    As[kc + 2][row] = f2tf(a0.z); As[kc + 3][row] = f2tf(a0.w);
    As[kc + 4][row] = f2tf(a1.x); As[kc + 5][row] = f2tf(a1.y);
    As[kc + 6][row] = f2tf(a1.z); As[kc + 7][row] = f2tf(a1.w);
    Bs[krow][nc + 0] = f2tf(b0.x); Bs[krow][nc + 1] = f2tf(b0.y);
    Bs[krow][nc + 2] = f2tf(b0.z); Bs[krow][nc + 3] = f2tf(b0.w);
    Bs[krow][nc + 4] = f2tf(b1.x); Bs[krow][nc + 5] = f2tf(b1.y);
    Bs[krow][nc + 6] = f2tf(b1.z); Bs[krow][nc + 7] = f2tf(b1.w);
    __syncthreads();

    int buf = 0;
    for (int it = 0; it < iters; it++) {
        if (it + 1 < iters) {
            const float* ap = aptr + (it + 1) * BK;
            a0 = *(const float4*)(ap);
            a1 = *(const float4*)(ap + 4);
            const float* bp = bptr + (size_t)(it + 1) * BK * ldb;
            b0 = *(const float4*)(bp);
            b1 = *(const float4*)(bp + 4);
        }
        uint32_t (*Ac)[LDSW] = As + buf * BK;
        uint32_t (*Bc)[LDSW] = Bs + buf * BK;
        #pragma unroll
        for (int ks = 0; ks < BK; ks += 8) {
            uint32_t bf[4][2];
            #pragma unroll
            for (int nf = 0; nf < 4; nf++) {
                int n0 = n0base + nf * 8 + g;
                bf[nf][0] = Bc[ks + c][n0];
                bf[nf][1] = Bc[ks + c + 4][n0];
            }
            #pragma unroll
            for (int mf = 0; mf < 4; mf++) {
                int m0 = m0base + mf * 16 + g;
                uint32_t fa0 = Ac[ks + c][m0];
                uint32_t fa1 = Ac[ks + c][m0 + 8];
                uint32_t fa2 = Ac[ks + c + 4][m0];
                uint32_t fa3 = Ac[ks + c + 4][m0 + 8];
                #pragma unroll
                for (int nf = 0; nf < 4; nf++)
                    mma_tf32(acc[mf * 4 + nf], fa0, fa1, fa2, fa3,
                             bf[nf][0], bf[nf][1]);
            }
        }
        if (it + 1 < iters) {
            uint32_t (*An)[LDSW] = As + (buf ^ 1) * BK;
            uint32_t (*Bn)[LDSW] = Bs + (buf ^ 1) * BK;
            An[kc + 0][row] = f2tf(a0.x); An[kc + 1][row] = f2tf(a0.y);
            An[kc + 2][row] = f2tf(a0.z); An[kc + 3][row] = f2tf(a0.w);
            An[kc + 4][row] = f2tf(a1.x); An[kc + 5][row] = f2tf(a1.y);
            An[kc + 6][row] = f2tf(a1.z); An[kc + 7][row] = f2tf(a1.w);
            Bn[krow][nc + 0] = f2tf(b0.x); Bn[krow][nc + 1] = f2tf(b0.y);
            Bn[krow][nc + 2] = f2tf(b0.z); Bn[krow][nc + 3] = f2tf(b0.w);
            Bn[krow][nc + 4] = f2tf(b1.x); Bn[krow][nc + 5] = f2tf(b1.y);
            Bn[krow][nc + 6] = f2tf(b1.z); Bn[krow][nc + 7] = f2tf(b1.w);
        }
        __syncthreads();
        buf ^= 1;
    }
}

#define MMA_PROLOG()                         \
    int t    = threadIdx.x;                  \
    int lane = t & 31;                       \
    int wid  = t >> 5;                       \
    int row  = t >> 1;                       \
    int kc   = (t & 1) * 8;                  \
    int krow = t >> 4;                       \
    int nc   = (t & 15) * 8;                 \
    int g    = lane >> 2;                    \
    int c    = lane & 3;                     \
    int wm   = wid & 1;                      \
    int wn   = wid >> 1;                     \
    int m0base = wm * 64;                    \
    int n0base = wn * 32;                    \
    __shared__ uint32_t As[2 * BK][LDSW];    \
    __shared__ uint32_t Bs[2 * BK][LDSW];    \
    float acc[16][4];                        \
    for (int _i = 0; _i < 16; _i++)          \
        for (int _j = 0; _j < 4; _j++) acc[_i][_j] = 0.f;

// ---------------------------------------------------------------------------
// Fused QKV projection: grid (Tn/128, Dn/128, 3)
// ---------------------------------------------------------------------------
__global__ void __launch_bounds__(256, 2)
qkv_gemm(const float* __restrict__ h1,
         const float* __restrict__ wq, const float* __restrict__ wk,
         const float* __restrict__ wv) {
    const float* W = (blockIdx.z == 0) ? wq : (blockIdx.z == 1) ? wk : wv;
    float* C = (blockIdx.z == 0) ? g_q : (blockIdx.z == 1) ? g_k : g_v;
    int bm = blockIdx.x * BM, bn = blockIdx.y * BN;
    MMA_PROLOG();
    gemm_core_tf32(h1 + (size_t)(bm + row) * Dn + kc,
                   W + (size_t)krow * Dn + bn + nc,
                   Dn, Dn / BK, acc, As, Bs, row, kc, krow, nc, g, c, m0base, n0base);
    #pragma unroll
    for (int mf = 0; mf < 4; mf++) {
        int r0 = bm + m0base + mf * 16 + g;
        #pragma unroll
        for (int nf = 0; nf < 4; nf++) {
            int cb = bn + n0base + nf * 8 + c * 2;
            float* cc = acc[mf * 4 + nf];
            *(float2*)(C + (size_t)r0 * Dn + cb)       = make_float2(cc[0], cc[1]);
            *(float2*)(C + (size_t)(r0 + 8) * Dn + cb) = make_float2(cc[2], cc[3]);
        }
    }
}

// ---------------------------------------------------------------------------
// O projection + residual: x1 = x + att @ wo.  grid (Tn/128, Dn/128)
// ---------------------------------------------------------------------------
__global__ void __launch_bounds__(256, 2)
oproj_gemm(const float* __restrict__ wo, const float* __restrict__ x) {
    int bm = blockIdx.x * BM, bn = blockIdx.y * BN;
    MMA_PROLOG();
    gemm_core_tf32(g_att + (size_t)(bm + row) * Dn + kc,
                   wo + (size_t)krow * Dn + bn + nc,
                   Dn, Dn / BK, acc, As, Bs, row, kc, krow, nc, g, c, m0base, n0base);
    #pragma unroll
    for (int mf = 0; mf < 4; mf++) {
        int r0 = bm + m0base + mf * 16 + g;
        #pragma unroll
        for (int nf = 0; nf < 4; nf++) {
            int cb = bn + n0base + nf * 8 + c * 2;
            float* cc = acc[mf * 4 + nf];
            size_t p0 = (size_t)r0 * Dn + cb;
            size_t p1 = (size_t)(r0 + 8) * Dn + cb;
            float2 x0 = *(const float2*)(x + p0);
            float2 x1v = *(const float2*)(x + p1);
            *(float2*)(g_x1 + p0) = make_float2(x0.x + cc[0], x0.y + cc[1]);
            *(float2*)(g_x1 + p1) = make_float2(x1v.x + cc[2], x1v.y + cc[3]);
        }
    }
}

// ---------------------------------------------------------------------------
// MoE FFN1: gathered rows, gelu(X@w1[e] + b1[e]) -> g_mid
// grid (Tn/128, Fn/128, E)
// ---------------------------------------------------------------------------
__global__ void __launch_bounds__(256, 2)
moe_ffn1(const float* __restrict__ h2, const float* __restrict__ w1,
         const float* __restrict__ b1) {
    int e = blockIdx.z;
    int cnt = g_counts[e];
    int bm = blockIdx.x * BM;
    if (bm >= cnt) return;
    int off = g_offsets[e];
    int bn = blockIdx.y * BN;
    MMA_PROLOG();
    int arow = bm + row; if (arow >= cnt) arow = cnt - 1;
    int tok = g_slot2tok[off + arow];
    gemm_core_tf32(h2 + (size_t)tok * Dn + kc,
                   w1 + (size_t)e * Dn * Fn + (size_t)krow * Fn + bn + nc,
                   Fn, Dn / BK, acc, As, Bs, row, kc, krow, nc, g, c, m0base, n0base);
    #pragma unroll
    for (int mf = 0; mf < 4; mf++) {
        int r0 = bm + m0base + mf * 16 + g;
        int r1 = r0 + 8;
        #pragma unroll
        for (int nf = 0; nf < 4; nf++) {
            int cb = bn + n0base + nf * 8 + c * 2;
            float bv0 = b1[e * Fn + cb], bv1 = b1[e * Fn + cb + 1];
            float* cc = acc[mf * 4 + nf];
            if (r0 < cnt)
                *(float2*)(g_mid + (size_t)(off + r0) * Fn + cb) =
                    make_float2(gelu_tanh(cc[0] + bv0), gelu_tanh(cc[1] + bv1));
            if (r1 < cnt)
                *(float2*)(g_mid + (size_t)(off + r1) * Fn + cb) =
                    make_float2(gelu_tanh(cc[2] + bv0), gelu_tanh(cc[3] + bv1));
        }
    }
}

// ---------------------------------------------------------------------------
// MoE FFN2: mid@w2[e] + b2[e] -> g_eout.  grid (Tn/128, Dn/128, E)
// ---------------------------------------------------------------------------
__global__ void __launch_bounds__(256, 2)
moe_ffn2(const float* __restrict__ w2, const float* __restrict__ b2) {
    int e = blockIdx.z;
    int cnt = g_counts[e];
    int bm = blockIdx.x * BM;
    if (bm >= cnt) return;
    int off = g_offsets[e];
    int bn = blockIdx.y * BN;
    MMA_PROLOG();
    int arow = bm + row; if (arow >= cnt) arow = cnt - 1;
    gemm_core_tf32(g_mid + (size_t)(off + arow) * Fn + kc,
                   w2 + (size_t)e * Fn * Dn + (size_t)krow * Dn + bn + nc,
                   Dn, Fn / BK, acc, As, Bs, row, kc, krow, nc, g, c, m0base, n0base);
    #pragma unroll
    for (int mf = 0; mf < 4; mf++) {
        int r0 = bm + m0base + mf * 16 + g;
        int r1 = r0 + 8;
        #pragma unroll
        for (int nf = 0; nf < 4; nf++) {
            int cb = bn + n0base + nf * 8 + c * 2;
            float bv0 = b2[e * Dn + cb], bv1 = b2[e * Dn + cb + 1];
            float* cc = acc[mf * 4 + nf];
            if (r0 < cnt)
                *(float2*)(g_eout + (size_t)(off + r0) * Dn + cb) =
                    make_float2(cc[0] + bv0, cc[1] + bv1);
            if (r1 < cnt)
                *(float2*)(g_eout + (size_t)(off + r1) * Dn + cb) =
                    make_float2(cc[2] + bv0, cc[3] + bv1);
        }
    }
}

// ---------------------------------------------------------------------------
// LayerNorm: one block per token, 256 threads, D=768 (3 elems/thread)
// ---------------------------------------------------------------------------
__global__ void ln_kernel(const float* __restrict__ x,
                          const float* __restrict__ g,
                          const float* __restrict__ b,
                          float* __restrict__ out) {
    int t = blockIdx.x;
    const float* row = x + (size_t)t * Dn;
    int tid = threadIdx.x;
    float v0 = row[tid], v1 = row[tid + 256], v2 = row[tid + 512];
    float s  = v0 + v1 + v2;
    float ss = v0 * v0 + v1 * v1 + v2 * v2;
    #pragma unroll
    for (int o = 16; o; o >>= 1) {
        s  += __shfl_down_sync(0xffffffffu, s, o);
        ss += __shfl_down_sync(0xffffffffu, ss, o);
    }
    __shared__ float rs[8], rss[8];
    __shared__ float mu_s, rstd_s;
    int w = tid >> 5, l = tid & 31;
    if (l == 0) { rs[w] = s; rss[w] = ss; }
    __syncthreads();
    if (tid == 0) {
        float S = 0.f, SS = 0.f;
        #pragma unroll
        for (int i = 0; i < 8; i++) { S += rs[i]; SS += rss[i]; }
        float mu  = S / (float)Dn;
        float var = SS / (float)Dn - mu * mu;
        mu_s = mu; rstd_s = rsqrtf(var + 1e-5f);
    }
    __syncthreads();
    float mu = mu_s, rstd = rstd_s;
    float* orow = out + (size_t)t * Dn;
    orow[tid]       = (v0 - mu) * rstd * g[tid]       + b[tid];
    orow[tid + 256] = (v1 - mu) * rstd * g[tid + 256] + b[tid + 256];
    orow[tid + 512] = (v2 - mu) * rstd * g[tid + 512] + b[tid + 512];
}

// ---------------------------------------------------------------------------
// Flash-style attention: grid (S/128, H, B), 128 threads; one thread = one q row.
// ---------------------------------------------------------------------------
__global__ void __launch_bounds__(128)
attn_kernel(const float* __restrict__ q, const float* __restrict__ k,
            const float* __restrict__ v, float* __restrict__ o_out) {
    const int KT = 32;
    int h = blockIdx.y, b = blockIdx.z;
    int tid = threadIdx.x;
    int qrow = b * Sn + blockIdx.x * 128 + tid;
    const float* qptr = q + (size_t)qrow * Dn + h * DHn;
    float qreg[64];
    #pragma unroll
    for (int d = 0; d < 64; d++) qreg[d] = qptr[d] * 0.125f;  // 1/sqrt(64)
    float oacc[64];
    #pragma unroll
    for (int d = 0; d < 64; d++) oacc[d] = 0.f;
    float m = -1e30f, lsum = 0.f;

    __shared__ float Ks[KT][64], Vs[KT][64];
    for (int k0 = 0; k0 < Sn; k0 += KT) {
        for (int i = tid; i < KT * 64; i += 128) {
            int r = i >> 6, ccol = i & 63;
            size_t src = (size_t)(b * Sn + k0 + r) * Dn + h * DHn + ccol;
            Ks[r][ccol] = k[src];
            Vs[r][ccol] = v[src];
        }
        __syncthreads();
        float sv[KT];
        float smax = -1e30f;
        #pragma unroll
        for (int j = 0; j < KT; j++) {
            float s = 0.f;
            #pragma unroll
            for (int d = 0; d < 64; d++) s += qreg[d] * Ks[j][d];
            sv[j] = s;
            smax = fmaxf(smax, s);
        }
        float mnew = fmaxf(m, smax);
        float alpha = expf(m - mnew);
        float psum = 0.f;
        #pragma unroll
        for (int j = 0; j < KT; j++) { float p = expf(sv[j] - mnew); sv[j] = p; psum += p; }
        lsum = lsum * alpha + psum;
        #pragma unroll
        for (int d = 0; d < 64; d++) {
            float a = 0.f;
            #pragma unroll
            for (int j = 0; j < KT; j++) a += sv[j] * Vs[j][d];
            oacc[d] = oacc[d] * alpha + a;
        }
        m = mnew;
        __syncthreads();
    }
    float inv = 1.0f / lsum;
    float* op = o_out + (size_t)qrow * Dn + h * DHn;
    #pragma unroll
    for (int d = 0; d < 64; d++) op[d] = oacc[d] * inv;
}

// ---------------------------------------------------------------------------
// MoE routing
// ---------------------------------------------------------------------------
__global__ void zero_counts_kernel() {
    if (threadIdx.x < En) g_counts[threadIdx.x] = 0;
}

__global__ void routing_kernel(const float* __restrict__ h2,
                               const float* __restrict__ gate_w,
                               const float* __restrict__ gate_b,
                               const float* __restrict__ bias_e) {
    int t = blockIdx.x;
    int wid = threadIdx.x >> 5, lane = threadIdx.x & 31;
    __shared__ float logit[En];
    float s = 0.f;
    const float* row = h2 + (size_t)t * Dn;
    for (int d = lane; d < Dn; d += 32) s += row[d] * gate_w[d * En + wid];
    #pragma unroll
    for (int o = 16; o; o >>= 1) s += __shfl_down_sync(0xffffffffu, s, o);
    if (lane == 0) logit[wid] = s + gate_b[wid];   // TAU = 1
    __syncthreads();
    if (threadIdx.x == 0) {
        float sel[En];
        #pragma unroll
        for (int e = 0; e < En; e++) sel[e] = logit[e] + bias_e[e];
        int i0 = 0;
        #pragma unroll
        for (int e = 1; e < En; e++) if (sel[e] > sel[i0]) i0 = e;
        int i1 = (i0 == 0) ? 1 : 0;
        #pragma unroll
        for (int e = 0; e < En; e++) if (e != i0 && sel[e] > sel[i1]) i1 = e;
        float l0 = logit[i0], l1 = logit[i1];
        float mm = fmaxf(l0, l1);
        float e0 = expf(l0 - mm), e1 = expf(l1 - mm);
        float inv = 1.0f / (e0 + e1);
        g_idx[t * 2] = i0;     g_idx[t * 2 + 1] = i1;
        g_gate[t * 2] = e0 * inv; g_gate[t * 2 + 1] = e1 * inv;
        g_pos[t * 2]     = atomicAdd(&g_counts[i0], 1);
        g_pos[t * 2 + 1] = atomicAdd(&g_counts[i1], 1);
    }
}

__global__ void offsets_kernel() {
    if (threadIdx.x == 0) {
        int acc = 0;
        for (int e = 0; e < En; e++) { g_offsets[e] = acc; acc += g_counts[e]; }
    }
}

__global__ void fill_slots_kernel() {
    int t = blockIdx.x * 256 + threadIdx.x;
    if (t >= Tn) return;
    #pragma unroll
    for (int kk = 0; kk < 2; kk++) {
        int e = g_idx[t * 2 + kk];
        int slot = g_offsets[e] + g_pos[t * 2 + kk];
        g_slotof[t * 2 + kk] = slot;
        g_slot2tok[slot] = t;
    }
}

// ---------------------------------------------------------------------------
// Final combine: out = x1 + g0*eout[slot0] + g1*eout[slot1]
// ---------------------------------------------------------------------------
__global__ void combine_kernel(const float* __restrict__ x1, float* __restrict__ out) {
    int t = blockIdx.x;
    int d = blockIdx.y * 256 + threadIdx.x;
    int s0 = g_slotof[t * 2], s1 = g_slotof[t * 2 + 1];
    float g0 = g_gate[t * 2], g1 = g_gate[t * 2 + 1];
    out[(size_t)t * Dn + d] = x1[(size_t)t * Dn + d]
                            + g0 * g_eout[(size_t)s0 * Dn + d]
                            + g1 * g_eout[(size_t)s1 * Dn + d];
}

// ---------------------------------------------------------------------------
// launch
// ---------------------------------------------------------------------------
extern "C" void kernel_launch(void* const* d_in, const int* in_sizes, int n_in,
                              void* d_out, int out_size) {
    const float* x      = (const float*)d_in[0];
    const float* wq     = (const float*)d_in[1];
    const float* wk     = (const float*)d_in[2];
    const float* wv     = (const float*)d_in[3];
    const float* wo     = (const float*)d_in[4];
    const float* ln1_g  = (const float*)d_in[5];
    const float* ln1_b  = (const float*)d_in[6];
    const float* ln2_g  = (const float*)d_in[7];
    const float* ln2_b  = (const float*)d_in[8];
    const float* gate_w = (const float*)d_in[9];
    const float* gate_b = (const float*)d_in[10];
    const float* bias_e = (const float*)d_in[11];
    const float* w1     = (const float*)d_in[12];
    const float* b1     = (const float*)d_in[13];
    const float* w2     = (const float*)d_in[14];
    const float* b2     = (const float*)d_in[15];
    float* out = (float*)d_out;

    float *h1, *qb, *kb, *vb, *att, *x1, *h2;
    cudaGetSymbolAddress((void**)&h1,  g_h1);
    cudaGetSymbolAddress((void**)&qb,  g_q);
    cudaGetSymbolAddress((void**)&kb,  g_k);
    cudaGetSymbolAddress((void**)&vb,  g_v);
    cudaGetSymbolAddress((void**)&att, g_att);
    cudaGetSymbolAddress((void**)&x1,  g_x1);
    cudaGetSymbolAddress((void**)&h2,  g_h2);

    // --- attention block ---
    ln_kernel<<<Tn, 256>>>(x, ln1_g, ln1_b, h1);
    qkv_gemm<<<dim3(Tn / BM, Dn / BN, 3), 256>>>(h1, wq, wk, wv);
    attn_kernel<<<dim3(Sn / 128, Hn, Bsz), 128>>>(qb, kb, vb, att);
    oproj_gemm<<<dim3(Tn / BM, Dn / BN), 256>>>(wo, x);

    // --- MoE block ---
    ln_kernel<<<Tn, 256>>>(x1, ln2_g, ln2_b, h2);
    zero_counts_kernel<<<1, 32>>>();
    routing_kernel<<<Tn, 256>>>(h2, gate_w, gate_b, bias_e);
    offsets_kernel<<<1, 32>>>();
    fill_slots_kernel<<<Tn / 256, 256>>>();
    moe_ffn1<<<dim3(Tn / BM, Fn / BN, En), 256>>>(h2, w1, b1);
    moe_ffn2<<<dim3(Tn / BM, Dn / BN, En), 256>>>(w2, b2);
    combine_kernel<<<dim3(Tn, Dn / 256), 256>>>(x1, out);
}

// round 7
// speedup vs baseline: 2.4672x; 1.0418x over previous
#include <cuda_runtime.h>
#include <math.h>
#include <stdint.h>

// ---- problem dims ----
#define Tn 4096      // B*S tokens
#define Dn 768
#define Hn 12
#define DHn 64
#define Sn 512
#define Bsz 8
#define En 8
#define Fn 3072
#define TOPK 2

#define BM 128
#define BN 128
#define BK 16
#define LDA 20    // A smem row stride (words); 20g+c is a bank permutation
#define LDB 136   // B smem row stride (words); 8c+g is a bank permutation

// ---- scratch (device globals: allocation-free per harness rules) ----
__device__ float g_h1[Tn * Dn];
__device__ float g_q[Tn * Dn];
__device__ float g_k[Tn * Dn];
__device__ float g_v[Tn * Dn];
__device__ float g_att[Tn * Dn];
__device__ float g_x1[Tn * Dn];
__device__ float g_h2r[Tn * Dn];                  // tf32-rounded (GEMM A)
__device__ float g_h2x[Tn * Dn];                  // exact (routing)
__device__ float g_mid[(size_t)Tn * TOPK * Fn];   // ~100 MB
__device__ float g_eout[Tn * TOPK * Dn];          // ~25 MB
// tf32-rounded weight copies
__device__ float g_wqr[Dn * Dn];
__device__ float g_wkr[Dn * Dn];
__device__ float g_wvr[Dn * Dn];
__device__ float g_wor[Dn * Dn];
__device__ float g_w1r[(size_t)En * Dn * Fn];     // 72 MB
__device__ float g_w2r[(size_t)En * Fn * Dn];     // 72 MB
__device__ int   g_idx[Tn * TOPK];
__device__ float g_gate[Tn * TOPK];
__device__ int   g_pos[Tn * TOPK];
__device__ int   g_slotof[Tn * TOPK];
__device__ int   g_slot2tok[Tn * TOPK];
__device__ int   g_counts[En];
__device__ int   g_offsets[En];

// ---- helpers ----
__device__ __forceinline__ float gelu_tanh(float x) {
    const float c = 0.7978845608028654f;   // sqrt(2/pi)
    float t = tanhf(c * (x + 0.044715f * x * x * x));
    return 0.5f * x * (1.0f + t);
}

__device__ __forceinline__ uint32_t f2tf(float x) {
    uint32_t r;
    asm("cvt.rna.tf32.f32 %0, %1;" : "=r"(r) : "f"(x));
    return r;
}
__device__ __forceinline__ float roundtf(float x) { return __uint_as_float(f2tf(x)); }

__device__ __forceinline__ void mma_tf32(float* cc,
    uint32_t a0, uint32_t a1, uint32_t a2, uint32_t a3,
    uint32_t b0, uint32_t b1) {
    asm volatile(
        "mma.sync.aligned.m16n8k8.row.col.f32.tf32.tf32.f32 "
        "{%0,%1,%2,%3},{%4,%5,%6,%7},{%8,%9},{%0,%1,%2,%3};"
        : "+f"(cc[0]), "+f"(cc[1]), "+f"(cc[2]), "+f"(cc[3])
        : "r"(a0), "r"(a1), "r"(a2), "r"(a3), "r"(b0), "r"(b1));
}

__device__ __forceinline__ uint32_t sptr(const void* p) {
    return (uint32_t)__cvta_generic_to_shared(p);
}
#define CP16(s, g) asm volatile("cp.async.cg.shared.global [%0], [%1], 16;" :: "r"(s), "l"(g))
#define CPCOMMIT() asm volatile("cp.async.commit_group;")
#define CPWAIT1()  asm volatile("cp.async.wait_group 1;")
#define CPWAIT0()  asm volatile("cp.async.wait_group 0;")

// ---------------------------------------------------------------------------
// tf32 tensor-core GEMM core, cp.async pipeline.
// 128x128 tile, BK=16, 256 threads (8 warps), warp tile 64x32
// (4 Mfrags x 4 Nfrags of m16n8k8), fp32 accumulate.
// Operands are PRE-ROUNDED to tf32 (raw bit copy here, no cvt in hot loop).
// Smem: As[2][128][LDA] row-major [m][k]; Bs[2][16][LDB] [k][n].
// Stage (per thread, per K-tile): A row ar cols ac..ac+7 (2x cp16);
//                                 B row bkr cols bc..bc+7 (2x cp16).
// Fragments (m16n8k8.tf32): g=lane>>2, c=lane&3
//   a0=(g,c) a1=(g+8,c) a2=(g,c+4) a3=(g+8,c+4)
//   b0=(c,g) b1=(c+4,g);  C rows {g,g+8}, cols {2c,2c+1}
// ---------------------------------------------------------------------------
__device__ __forceinline__ void gemm_core_async(
    const float* __restrict__ arow,   // A base + (staging row)*lda
    const float* __restrict__ bcol,   // B base + bn + bc
    int ldb, int iters,
    float (&acc)[16][4],
    float (*As)[BM][LDA], float (*Bs)[BK][LDB],
    int ar, int ac, int bkr, int bc,
    int g, int c, int m0base, int n0base)
{
    uint32_t a_s0 = sptr(&As[0][ar][ac]);
    uint32_t a_s1 = sptr(&As[1][ar][ac]);
    uint32_t b_s0 = sptr(&Bs[0][bkr][bc]);
    uint32_t b_s1 = sptr(&Bs[1][bkr][bc]);
    const float* ag = arow + ac;
    const float* bg = bcol + (size_t)bkr * ldb;

    CP16(a_s0, ag); CP16(a_s0 + 16, ag + 4);
    CP16(b_s0, bg); CP16(b_s0 + 16, bg + 4);
    CPCOMMIT();

    int buf = 0;
    for (int it = 0; it < iters; it++) {
        if (it + 1 < iters) {
            const float* ag2 = ag + (it + 1) * BK;
            const float* bg2 = bg + (size_t)(it + 1) * BK * ldb;
            uint32_t asn = buf ? a_s0 : a_s1;
            uint32_t bsn = buf ? b_s0 : b_s1;
            CP16(asn, ag2); CP16(asn + 16, ag2 + 4);
            CP16(bsn, bg2); CP16(bsn + 16, bg2 + 4);
            CPCOMMIT();
            CPWAIT1();
        } else {
            CPWAIT0();
        }
        __syncthreads();
        #pragma unroll
        for (int ks = 0; ks < BK; ks += 8) {
            uint32_t bf[4][2];
            #pragma unroll
            for (int nf = 0; nf < 4; nf++) {
                int n0 = n0base + nf * 8 + g;
                bf[nf][0] = __float_as_uint(Bs[buf][ks + c][n0]);
                bf[nf][1] = __float_as_uint(Bs[buf][ks + c + 4][n0]);
            }
            #pragma unroll
            for (int mf = 0; mf < 4; mf++) {
                int m0 = m0base + mf * 16 + g;
                uint32_t fa0 = __float_as_uint(As[buf][m0][ks + c]);
                uint32_t fa1 = __float_as_uint(As[buf][m0 + 8][ks + c]);
                uint32_t fa2 = __float_as_uint(As[buf][m0][ks + c + 4]);
                uint32_t fa3 = __float_as_uint(As[buf][m0 + 8][ks + c + 4]);
                #pragma unroll
                for (int nf = 0; nf < 4; nf++)
                    mma_tf32(acc[mf * 4 + nf], fa0, fa1, fa2, fa3,
                             bf[nf][0], bf[nf][1]);
            }
        }
        __syncthreads();
        buf ^= 1;
    }
}

#define MMA_PROLOG()                              \
    int t    = threadIdx.x;                       \
    int lane = t & 31;                            \
    int wid  = t >> 5;                            \
    int ar   = t >> 1;                            \
    int ac   = (t & 1) * 8;                       \
    int bkr  = t >> 4;                            \
    int bc   = (t & 15) * 8;                      \
    int g    = lane >> 2;                         \
    int c    = lane & 3;                          \
    int m0base = (wid & 1) * 64;                  \
    int n0base = (wid >> 1) * 32;                 \
    __shared__ float As[2][BM][LDA];              \
    __shared__ float Bs[2][BK][LDB];              \
    float acc[16][4];                             \
    _Pragma("unroll")                             \
    for (int _i = 0; _i < 16; _i++)               \
        for (int _j = 0; _j < 4; _j++) acc[_i][_j] = 0.f;

// ---------------------------------------------------------------------------
// Weight tf32 pre-round: out[i] = round_tf32(in[i]), float4 vectorized
// ---------------------------------------------------------------------------
__global__ void round4_kernel(const float* __restrict__ in, float* __restrict__ outp, int n4) {
    int i = blockIdx.x * 256 + threadIdx.x;
    if (i >= n4) return;
    float4 v = ((const float4*)in)[i];
    v.x = roundtf(v.x); v.y = roundtf(v.y); v.z = roundtf(v.z); v.w = roundtf(v.w);
    ((float4*)outp)[i] = v;
}

// ---------------------------------------------------------------------------
// Fused QKV projection: grid (Tn/128, Dn/128, 3)
// ---------------------------------------------------------------------------
__global__ void __launch_bounds__(256, 2)
qkv_gemm(const float* __restrict__ h1) {
    const float* W = (blockIdx.z == 0) ? g_wqr : (blockIdx.z == 1) ? g_wkr : g_wvr;
    float* C = (blockIdx.z == 0) ? g_q : (blockIdx.z == 1) ? g_k : g_v;
    int bm = blockIdx.x * BM, bn = blockIdx.y * BN;
    MMA_PROLOG();
    gemm_core_async(h1 + (size_t)(bm + ar) * Dn,
                    W + bn + bc,
                    Dn, Dn / BK, acc, As, Bs, ar, ac, bkr, bc, g, c, m0base, n0base);
    #pragma unroll
    for (int mf = 0; mf < 4; mf++) {
        int r0 = bm + m0base + mf * 16 + g;
        #pragma unroll
        for (int nf = 0; nf < 4; nf++) {
            int cb = bn + n0base + nf * 8 + c * 2;
            float* cc = acc[mf * 4 + nf];
            *(float2*)(C + (size_t)r0 * Dn + cb)       = make_float2(cc[0], cc[1]);
            *(float2*)(C + (size_t)(r0 + 8) * Dn + cb) = make_float2(cc[2], cc[3]);
        }
    }
}

// ---------------------------------------------------------------------------
// O projection + residual: x1 = x + att @ wo.  grid (Tn/128, Dn/128)
// ---------------------------------------------------------------------------
__global__ void __launch_bounds__(256, 2)
oproj_gemm(const float* __restrict__ x) {
    int bm = blockIdx.x * BM, bn = blockIdx.y * BN;
    MMA_PROLOG();
    gemm_core_async(g_att + (size_t)(bm + ar) * Dn,
                    g_wor + bn + bc,
                    Dn, Dn / BK, acc, As, Bs, ar, ac, bkr, bc, g, c, m0base, n0base);
    #pragma unroll
    for (int mf = 0; mf < 4; mf++) {
        int r0 = bm + m0base + mf * 16 + g;
        #pragma unroll
        for (int nf = 0; nf < 4; nf++) {
            int cb = bn + n0base + nf * 8 + c * 2;
            float* cc = acc[mf * 4 + nf];
            size_t p0 = (size_t)r0 * Dn + cb;
            size_t p1 = (size_t)(r0 + 8) * Dn + cb;
            float2 x0 = *(const float2*)(x + p0);
            float2 x1v = *(const float2*)(x + p1);
            *(float2*)(g_x1 + p0) = make_float2(x0.x + cc[0], x0.y + cc[1]);
            *(float2*)(g_x1 + p1) = make_float2(x1v.x + cc[2], x1v.y + cc[3]);
        }
    }
}

// ---------------------------------------------------------------------------
// MoE FFN1: gathered rows, gelu(X@w1[e] + b1[e]) -> g_mid (tf32-rounded)
// grid (Tn/128, Fn/128, E)
// ---------------------------------------------------------------------------
__global__ void __launch_bounds__(256, 2)
moe_ffn1(const float* __restrict__ b1) {
    int e = blockIdx.z;
    int cnt = g_counts[e];
    int bm = blockIdx.x * BM;
    if (bm >= cnt) return;
    int off = g_offsets[e];
    int bn = blockIdx.y * BN;
    MMA_PROLOG();
    int arow = bm + ar; if (arow >= cnt) arow = cnt - 1;
    int tok = g_slot2tok[off + arow];
    gemm_core_async(g_h2r + (size_t)tok * Dn,
                    g_w1r + (size_t)e * Dn * Fn + bn + bc,
                    Fn, Dn / BK, acc, As, Bs, ar, ac, bkr, bc, g, c, m0base, n0base);
    #pragma unroll
    for (int mf = 0; mf < 4; mf++) {
        int r0 = bm + m0base + mf * 16 + g;
        int r1 = r0 + 8;
        #pragma unroll
        for (int nf = 0; nf < 4; nf++) {
            int cb = bn + n0base + nf * 8 + c * 2;
            float bv0 = b1[e * Fn + cb], bv1 = b1[e * Fn + cb + 1];
            float* cc = acc[mf * 4 + nf];
            if (r0 < cnt)
                *(float2*)(g_mid + (size_t)(off + r0) * Fn + cb) =
                    make_float2(roundtf(gelu_tanh(cc[0] + bv0)),
                                roundtf(gelu_tanh(cc[1] + bv1)));
            if (r1 < cnt)
                *(float2*)(g_mid + (size_t)(off + r1) * Fn + cb) =
                    make_float2(roundtf(gelu_tanh(cc[2] + bv0)),
                                roundtf(gelu_tanh(cc[3] + bv1)));
        }
    }
}

// ---------------------------------------------------------------------------
// MoE FFN2: mid@w2[e] + b2[e] -> g_eout.  grid (Tn/128, Dn/128, E)
// ---------------------------------------------------------------------------
__global__ void __launch_bounds__(256, 2)
moe_ffn2(const float* __restrict__ b2) {
    int e = blockIdx.z;
    int cnt = g_counts[e];
    int bm = blockIdx.x * BM;
    if (bm >= cnt) return;
    int off = g_offsets[e];
    int bn = blockIdx.y * BN;
    MMA_PROLOG();
    int arow = bm + ar; if (arow >= cnt) arow = cnt - 1;
    gemm_core_async(g_mid + (size_t)(off + arow) * Fn,
                    g_w2r + (size_t)e * Fn * Dn + bn + bc,
                    Dn, Fn / BK, acc, As, Bs, ar, ac, bkr, bc, g, c, m0base, n0base);
    #pragma unroll
    for (int mf = 0; mf < 4; mf++) {
        int r0 = bm + m0base + mf * 16 + g;
        int r1 = r0 + 8;
        #pragma unroll
        for (int nf = 0; nf < 4; nf++) {
            int cb = bn + n0base + nf * 8 + c * 2;
            float bv0 = b2[e * Dn + cb], bv1 = b2[e * Dn + cb + 1];
            float* cc = acc[mf * 4 + nf];
            if (r0 < cnt)
                *(float2*)(g_eout + (size_t)(off + r0) * Dn + cb) =
                    make_float2(cc[0] + bv0, cc[1] + bv1);
            if (r1 < cnt)
                *(float2*)(g_eout + (size_t)(off + r1) * Dn + cb) =
                    make_float2(cc[2] + bv0, cc[3] + bv1);
        }
    }
}

// ---------------------------------------------------------------------------
// LayerNorm: one block per token, 256 threads, D=768 (3 elems/thread).
// out = tf32-rounded LN (feeds GEMM A); out2 (optional) = exact LN (routing).
// ---------------------------------------------------------------------------
__global__ void ln_kernel(const float* __restrict__ x,
                          const float* __restrict__ g,
                          const float* __restrict__ b,
                          float* __restrict__ out,
                          float* __restrict__ out2) {
    int t = blockIdx.x;
    const float* row = x + (size_t)t * Dn;
    int tid = threadIdx.x;
    float v0 = row[tid], v1 = row[tid + 256], v2 = row[tid + 512];
    float s  = v0 + v1 + v2;
    float ss = v0 * v0 + v1 * v1 + v2 * v2;
    #pragma unroll
    for (int o = 16; o; o >>= 1) {
        s  += __shfl_down_sync(0xffffffffu, s, o);
        ss += __shfl_down_sync(0xffffffffu, ss, o);
    }
    __shared__ float rs[8], rss[8];
    __shared__ float mu_s, rstd_s;
    int w = tid >> 5, l = tid & 31;
    if (l == 0) { rs[w] = s; rss[w] = ss; }
    __syncthreads();
    if (tid == 0) {
        float S = 0.f, SS = 0.f;
        #pragma unroll
        for (int i = 0; i < 8; i++) { S += rs[i]; SS += rss[i]; }
        float mu  = S / (float)Dn;
        float var = SS / (float)Dn - mu * mu;
        mu_s = mu; rstd_s = rsqrtf(var + 1e-5f);
    }
    __syncthreads();
    float mu = mu_s, rstd = rstd_s;
    float* orow = out + (size_t)t * Dn;
    float e0 = (v0 - mu) * rstd * g[tid]       + b[tid];
    float e1 = (v1 - mu) * rstd * g[tid + 256] + b[tid + 256];
    float e2 = (v2 - mu) * rstd * g[tid + 512] + b[tid + 512];
    orow[tid]       = roundtf(e0);
    orow[tid + 256] = roundtf(e1);
    orow[tid + 512] = roundtf(e2);
    if (out2) {
        float* xrow = out2 + (size_t)t * Dn;
        xrow[tid] = e0; xrow[tid + 256] = e1; xrow[tid + 512] = e2;
    }
}

// ---------------------------------------------------------------------------
// Flash-style attention: grid (S/128, H, B), 128 threads; one thread = one q row.
// Output tf32-rounded (feeds oproj A).
// ---------------------------------------------------------------------------
__global__ void __launch_bounds__(128)
attn_kernel(const float* __restrict__ q, const float* __restrict__ k,
            const float* __restrict__ v, float* __restrict__ o_out) {
    const int KT = 32;
    int h = blockIdx.y, b = blockIdx.z;
    int tid = threadIdx.x;
    int qrow = b * Sn + blockIdx.x * 128 + tid;
    const float* qptr = q + (size_t)qrow * Dn + h * DHn;
    float qreg[64];
    #pragma unroll
    for (int d = 0; d < 64; d++) qreg[d] = qptr[d] * 0.125f;  // 1/sqrt(64)
    float oacc[64];
    #pragma unroll
    for (int d = 0; d < 64; d++) oacc[d] = 0.f;
    float m = -1e30f, lsum = 0.f;

    __shared__ float Ks[KT][64], Vs[KT][64];
    for (int k0 = 0; k0 < Sn; k0 += KT) {
        for (int i = tid; i < KT * 64; i += 128) {
            int r = i >> 6, ccol = i & 63;
            size_t src = (size_t)(b * Sn + k0 + r) * Dn + h * DHn + ccol;
            Ks[r][ccol] = k[src];
            Vs[r][ccol] = v[src];
        }
        __syncthreads();
        float sv[KT];
        float smax = -1e30f;
        #pragma unroll
        for (int j = 0; j < KT; j++) {
            float s = 0.f;
            #pragma unroll
            for (int d = 0; d < 64; d++) s += qreg[d] * Ks[j][d];
            sv[j] = s;
            smax = fmaxf(smax, s);
        }
        float mnew = fmaxf(m, smax);
        float alpha = expf(m - mnew);
        float psum = 0.f;
        #pragma unroll
        for (int j = 0; j < KT; j++) { float p = expf(sv[j] - mnew); sv[j] = p; psum += p; }
        lsum = lsum * alpha + psum;
        #pragma unroll
        for (int d = 0; d < 64; d++) {
            float a = 0.f;
            #pragma unroll
            for (int j = 0; j < KT; j++) a += sv[j] * Vs[j][d];
            oacc[d] = oacc[d] * alpha + a;
        }
        m = mnew;
        __syncthreads();
    }
    float inv = 1.0f / lsum;
    float* op = o_out + (size_t)qrow * Dn + h * DHn;
    #pragma unroll
    for (int d = 0; d < 64; d++) op[d] = roundtf(oacc[d] * inv);
}

// ---------------------------------------------------------------------------
// MoE routing (reads EXACT h2 + exact gate_w: selection identical to reference)
// ---------------------------------------------------------------------------
__global__ void zero_counts_kernel() {
    if (threadIdx.x < En) g_counts[threadIdx.x] = 0;
}

__global__ void routing_kernel(const float* __restrict__ h2,
                               const float* __restrict__ gate_w,
                               const float* __restrict__ gate_b,
                               const float* __restrict__ bias_e) {
    int t = blockIdx.x;
    int wid = threadIdx.x >> 5, lane = threadIdx.x & 31;
    __shared__ float logit[En];
    float s = 0.f;
    const float* row = h2 + (size_t)t * Dn;
    for (int d = lane; d < Dn; d += 32) s += row[d] * gate_w[d * En + wid];
    #pragma unroll
    for (int o = 16; o; o >>= 1) s += __shfl_down_sync(0xffffffffu, s, o);
    if (lane == 0) logit[wid] = s + gate_b[wid];   // TAU = 1
    __syncthreads();
    if (threadIdx.x == 0) {
        float sel[En];
        #pragma unroll
        for (int e = 0; e < En; e++) sel[e] = logit[e] + bias_e[e];
        int i0 = 0;
        #pragma unroll
        for (int e = 1; e < En; e++) if (sel[e] > sel[i0]) i0 = e;
        int i1 = (i0 == 0) ? 1 : 0;
        #pragma unroll
        for (int e = 0; e < En; e++) if (e != i0 && sel[e] > sel[i1]) i1 = e;
        float l0 = logit[i0], l1 = logit[i1];
        float mm = fmaxf(l0, l1);
        float e0 = expf(l0 - mm), e1 = expf(l1 - mm);
        float inv = 1.0f / (e0 + e1);
        g_idx[t * 2] = i0;     g_idx[t * 2 + 1] = i1;
        g_gate[t * 2] = e0 * inv; g_gate[t * 2 + 1] = e1 * inv;
        g_pos[t * 2]     = atomicAdd(&g_counts[i0], 1);
        g_pos[t * 2 + 1] = atomicAdd(&g_counts[i1], 1);
    }
}

__global__ void offsets_kernel() {
    if (threadIdx.x == 0) {
        int acc = 0;
        for (int e = 0; e < En; e++) { g_offsets[e] = acc; acc += g_counts[e]; }
    }
}

__global__ void fill_slots_kernel() {
    int t = blockIdx.x * 256 + threadIdx.x;
    if (t >= Tn) return;
    #pragma unroll
    for (int kk = 0; kk < 2; kk++) {
        int e = g_idx[t * 2 + kk];
        int slot = g_offsets[e] + g_pos[t * 2 + kk];
        g_slotof[t * 2 + kk] = slot;
        g_slot2tok[slot] = t;
    }
}

// ---------------------------------------------------------------------------
// Final combine: out = x1 + g0*eout[slot0] + g1*eout[slot1]
// ---------------------------------------------------------------------------
__global__ void combine_kernel(const float* __restrict__ x1, float* __restrict__ out) {
    int t = blockIdx.x;
    int d = blockIdx.y * 256 + threadIdx.x;
    int s0 = g_slotof[t * 2], s1 = g_slotof[t * 2 + 1];
    float g0 = g_gate[t * 2], g1 = g_gate[t * 2 + 1];
    out[(size_t)t * Dn + d] = x1[(size_t)t * Dn + d]
                            + g0 * g_eout[(size_t)s0 * Dn + d]
                            + g1 * g_eout[(size_t)s1 * Dn + d];
}

// ---------------------------------------------------------------------------
// launch
// ---------------------------------------------------------------------------
extern "C" void kernel_launch(void* const* d_in, const int* in_sizes, int n_in,
                              void* d_out, int out_size) {
    const float* x      = (const float*)d_in[0];
    const float* wq     = (const float*)d_in[1];
    const float* wk     = (const float*)d_in[2];
    const float* wv     = (const float*)d_in[3];
    const float* wo     = (const float*)d_in[4];
    const float* ln1_g  = (const float*)d_in[5];
    const float* ln1_b  = (const float*)d_in[6];
    const float* ln2_g  = (const float*)d_in[7];
    const float* ln2_b  = (const float*)d_in[8];
    const float* gate_w = (const float*)d_in[9];
    const float* gate_b = (const float*)d_in[10];
    const float* bias_e = (const float*)d_in[11];
    const float* w1     = (const float*)d_in[12];
    const float* b1     = (const float*)d_in[13];
    const float* w2     = (const float*)d_in[14];
    const float* b2     = (const float*)d_in[15];
    float* out = (float*)d_out;

    float *h1, *qb, *kb, *vb, *att, *x1, *h2r, *h2x;
    float *wqr, *wkr, *wvr, *wor, *w1r, *w2r;
    cudaGetSymbolAddress((void**)&h1,  g_h1);
    cudaGetSymbolAddress((void**)&qb,  g_q);
    cudaGetSymbolAddress((void**)&kb,  g_k);
    cudaGetSymbolAddress((void**)&vb,  g_v);
    cudaGetSymbolAddress((void**)&att, g_att);
    cudaGetSymbolAddress((void**)&x1,  g_x1);
    cudaGetSymbolAddress((void**)&h2r, g_h2r);
    cudaGetSymbolAddress((void**)&h2x, g_h2x);
    cudaGetSymbolAddress((void**)&wqr, g_wqr);
    cudaGetSymbolAddress((void**)&wkr, g_wkr);
    cudaGetSymbolAddress((void**)&wvr, g_wvr);
    cudaGetSymbolAddress((void**)&wor, g_wor);
    cudaGetSymbolAddress((void**)&w1r, g_w1r);
    cudaGetSymbolAddress((void**)&w2r, g_w2r);

    // --- tf32 pre-round of weights ---
    const int DD4 = Dn * Dn / 4;                  // 147456
    const int W4  = En * Dn * Fn / 4;             // 4718592
    round4_kernel<<<(DD4 + 255) / 256, 256>>>(wq, wqr, DD4);
    round4_kernel<<<(DD4 + 255) / 256, 256>>>(wk, wkr, DD4);
    round4_kernel<<<(DD4 + 255) / 256, 256>>>(wv, wvr, DD4);
    round4_kernel<<<(DD4 + 255) / 256, 256>>>(wo, wor, DD4);
    round4_kernel<<<(W4 + 255) / 256, 256>>>(w1, w1r, W4);
    round4_kernel<<<(W4 + 255) / 256, 256>>>(w2, w2r, W4);

    // --- attention block ---
    ln_kernel<<<Tn, 256>>>(x, ln1_g, ln1_b, h1, nullptr);
    qkv_gemm<<<dim3(Tn / BM, Dn / BN, 3), 256>>>(h1);
    attn_kernel<<<dim3(Sn / 128, Hn, Bsz), 128>>>(qb, kb, vb, att);
    oproj_gemm<<<dim3(Tn / BM, Dn / BN), 256>>>(x);

    // --- MoE block ---
    ln_kernel<<<Tn, 256>>>(x1, ln2_g, ln2_b, h2r, h2x);
    zero_counts_kernel<<<1, 32>>>();
    routing_kernel<<<Tn, 256>>>(h2x, gate_w, gate_b, bias_e);
    offsets_kernel<<<1, 32>>>();
    fill_slots_kernel<<<Tn / 256, 256>>>();
    moe_ffn1<<<dim3(Tn / BM, Fn / BN, En), 256>>>(b1);
    moe_ffn2<<<dim3(Tn / BM, Dn / BN, En), 256>>>(b2);
    combine_kernel<<<dim3(Tn, Dn / 256), 256>>>(x1, out);
}